// round 14
// baseline (speedup 1.0000x reference)
#include <cuda_runtime.h>
#include <cuda_fp16.h>
#include <math.h>
#include <stdint.h>

#define B_ 8
#define T_ 64
#define N_ 256
#define H_ 8
#define D_ 64
#define FEAT 512
#define TOKENS (B_*T_*N_)          /* 131072 */
#define ELEMS  (TOKENS*FEAT)       /* 67108864 */
#define WSZ    (512*512)

// ---------------------------------------------------------------------------
// Scratch (device globals — no cudaMalloc allowed). All-fp16 intermediates.
// ---------------------------------------------------------------------------
__device__ __half g_hf[10ull * ELEMS];
__device__ __half g_wt[6 * WSZ];      // K-major fp16 weights

// ---------------------------------------------------------------------------
// Helpers
// ---------------------------------------------------------------------------
__device__ __forceinline__ uint32_t smem_u32(const void* p) {
    uint32_t a;
    asm("{ .reg .u64 t; cvta.to.shared.u64 t, %1; cvt.u32.u64 %0, t; }" : "=r"(a) : "l"(p));
    return a;
}

__device__ __forceinline__ void cp16(uint32_t dst, const void* src) {
    asm volatile("cp.async.cg.shared.global [%0], [%1], 16;"
                 :: "r"(dst), "l"(__cvta_generic_to_global(src)));
}

__device__ __forceinline__ void ldsm4(uint32_t addr, uint32_t* r) {
    asm volatile("ldmatrix.sync.aligned.m8n8.x4.shared.b16 {%0,%1,%2,%3}, [%4];"
                 : "=r"(r[0]), "=r"(r[1]), "=r"(r[2]), "=r"(r[3]) : "r"(addr));
}

__device__ __forceinline__ void ldsm4t(uint32_t addr, uint32_t* r) {
    asm volatile("ldmatrix.sync.aligned.m8n8.x4.trans.shared.b16 {%0,%1,%2,%3}, [%4];"
                 : "=r"(r[0]), "=r"(r[1]), "=r"(r[2]), "=r"(r[3]) : "r"(addr));
}

__device__ __forceinline__ void mma_fp16(float* d, const uint32_t* a,
                                         uint32_t b0, uint32_t b1) {
    asm volatile(
        "mma.sync.aligned.m16n8k16.row.col.f32.f16.f16.f32 "
        "{%0,%1,%2,%3}, {%4,%5,%6,%7}, {%8,%9}, {%0,%1,%2,%3};"
        : "+f"(d[0]), "+f"(d[1]), "+f"(d[2]), "+f"(d[3])
        : "r"(a[0]), "r"(a[1]), "r"(a[2]), "r"(a[3]), "r"(b0), "r"(b1));
}

// ---------------------------------------------------------------------------
// Weight prep: transpose to K-major fp16. Wt[z][n][k] = fp16(W_z[k][n]).
// ---------------------------------------------------------------------------
__global__ __launch_bounds__(256)
void prep_w(const float* W0, const float* W1, const float* W2,
            const float* W3, const float* W4, const float* W5,
            __half* __restrict__ Wt)
{
    const float* Ws[6] = {W0, W1, W2, W3, W4, W5};
    const float* W = Ws[blockIdx.z];
    __shared__ float t[32][33];
    int bx = blockIdx.x * 32, by = blockIdx.y * 32;
#pragma unroll
    for (int r = 0; r < 32; r += 8)
        t[threadIdx.y + r][threadIdx.x] =
            W[(size_t)(by + threadIdx.y + r) * 512 + bx + threadIdx.x];
    __syncthreads();
    size_t base = (size_t)blockIdx.z * WSZ;
#pragma unroll
    for (int r = 0; r < 32; r += 8)
        Wt[base + (size_t)(bx + threadIdx.y + r) * 512 + by + threadIdx.x] =
            __float2half_rn(t[threadIdx.x][threadIdx.y + r]);
}

// ---------------------------------------------------------------------------
// Fused residual adds: s0 = fp16(xl+te), s1 = fp16(xh+te).
// ---------------------------------------------------------------------------
__global__ __launch_bounds__(256)
void add_te01(const float4* __restrict__ xl, const float4* __restrict__ xh,
              const float4* __restrict__ te,
              __half2* __restrict__ o0, __half2* __restrict__ o1)
{
    int i = blockIdx.x * 256 + threadIdx.x;
    float4 t = te[i];
    float4 a = xl[i];
    float4 b = xh[i];
    o0[2 * i]     = __floats2half2_rn(a.x + t.x, a.y + t.y);
    o0[2 * i + 1] = __floats2half2_rn(a.z + t.z, a.w + t.w);
    o1[2 * i]     = __floats2half2_rn(b.x + t.x, b.y + t.y);
    o1[2 * i + 1] = __floats2half2_rn(b.z + t.z, b.w + t.w);
}

// ---------------------------------------------------------------------------
// FP16 tensor-core GEMM, K-chunk 64, 2-stage cp.async (8 outer iterations:
// half the barriers/waits of the K32 version). CTA 128x128, 128 thr, 4 warps
// (64x64). Rows of 64 halves = 128B, 16B-chunk swizzle q^(row&7) (same
// addressing as the proven attention kernel). Triple operand set via
// blockIdx.x>>2. Output fp16 (+bias, optional relu).
// smem: (A 16KB + B 16KB) x 2 stages = 64KB dynamic.
// ---------------------------------------------------------------------------
__global__ __launch_bounds__(128, 2)
void gemm_fp16(const __half* __restrict__ A0, const __half* __restrict__ A1,
               const __half* B0, const float* bias0, __half* C0, int relu0,
               const __half* B1, const float* bias1, __half* C1, int relu1,
               const __half* B2, const float* bias2, __half* C2, int relu2)
{
    extern __shared__ __align__(128) unsigned char smem[];
    const uint32_t sb = smem_u32(smem);

    const int tid  = threadIdx.x;
    const int lane = tid & 31;
    const int warp = tid >> 5;
    const int wm = warp >> 1, wn = warp & 1;
    const int m0 = blockIdx.y * 128;

    const int set = blockIdx.x >> 2;
    const int n0  = (blockIdx.x & 3) * 128;

    const __half* AU = (set == 0) ? A0 : A1;
    const __half* BU = (set == 0) ? B0 : ((set == 1) ? B1 : B2);
    const float* biasU = (set == 0) ? bias0 : ((set == 1) ? bias1 : bias2);
    __half* CU = (set == 0) ? C0 : ((set == 1) ? C1 : C2);
    const int reluU = (set == 0) ? relu0 : ((set == 1) ? relu1 : relu2);

    const __half* Ag = AU + (size_t)m0 * 512;
    const __half* Bg = BU + (size_t)n0 * 512;

    // fill coords: 128 rows x 8 chunks per matrix, 128 threads -> 8 each
    int frow[8], fq[8];
    uint32_t foff[8];
#pragma unroll
    for (int j = 0; j < 8; j++) {
        int lin = tid + j * 128;
        frow[j] = lin >> 3;
        fq[j]   = lin & 7;
        foff[j] = frow[j] * 128 + ((uint32_t)(fq[j] ^ (frow[j] & 7)) << 4);
    }

#define FILL(kc, st)                                                          \
    do {                                                                      \
        uint32_t s_ = sb + (st) * 32768;                                      \
        _Pragma("unroll")                                                     \
        for (int j = 0; j < 8; j++) {                                         \
            size_t g_ = (size_t)frow[j] * 512 + (kc) * 64 + fq[j] * 8;        \
            cp16(s_ + foff[j],          Ag + g_);                             \
            cp16(s_ + 16384 + foff[j],  Bg + g_);                             \
        }                                                                     \
        asm volatile("cp.async.commit_group;");                               \
    } while (0)

    float acc[4][8][4];
#pragma unroll
    for (int i = 0; i < 4; i++)
#pragma unroll
        for (int j = 0; j < 8; j++)
#pragma unroll
            for (int k = 0; k < 4; k++) acc[i][j][k] = 0.f;

    const int rA_base = wm * 64 + (lane & 7) + ((lane >> 3) & 1) * 8;
    const int kqA = lane >> 4;             // +2*ks
    const int rB_base = wn * 64 + (lane & 7) + ((lane >> 4) & 1) * 8;
    const int kqB = (lane >> 3) & 1;       // +2*ks

    FILL(0, 0);
    FILL(1, 1);

    for (int c = 0; c < 8; c++) {
        if (c < 7) asm volatile("cp.async.wait_group 1;");
        else       asm volatile("cp.async.wait_group 0;");
        __syncthreads();

        const uint32_t sA = sb + (c & 1) * 32768;
        const uint32_t sB = sA + 16384;

#pragma unroll
        for (int ks = 0; ks < 4; ks++) {
            uint32_t ah[4][4], bh[4][4];
#pragma unroll
            for (int mt = 0; mt < 4; mt++) {
                int r = rA_base + mt * 16;
                int kq = ks * 2 + kqA;
                ldsm4(sA + r * 128 + ((kq ^ (r & 7)) << 4), ah[mt]);
            }
#pragma unroll
            for (int p = 0; p < 4; p++) {
                int r = rB_base + p * 16;
                int kq = ks * 2 + kqB;
                ldsm4(sB + r * 128 + ((kq ^ (r & 7)) << 4), bh[p]);
            }
#pragma unroll
            for (int mt = 0; mt < 4; mt++)
#pragma unroll
                for (int p = 0; p < 4; p++) {
                    mma_fp16(acc[mt][2 * p],     ah[mt], bh[p][0], bh[p][1]);
                    mma_fp16(acc[mt][2 * p + 1], ah[mt], bh[p][2], bh[p][3]);
                }
        }
        __syncthreads();
        if (c + 2 < 8) FILL(c + 2, (c & 1));
    }

    // ---- epilogue: bias (+relu), fp16 stores ----
#pragma unroll
    for (int mt = 0; mt < 4; mt++) {
        int row = m0 + wm * 64 + mt * 16 + (lane >> 2);
#pragma unroll
        for (int nt = 0; nt < 8; nt++) {
            int col = n0 + wn * 64 + nt * 8 + (lane & 3) * 2;
            float2 bb = __ldg((const float2*)(biasU + col));
            float v0 = acc[mt][nt][0] + bb.x;
            float v1 = acc[mt][nt][1] + bb.y;
            float v2 = acc[mt][nt][2] + bb.x;
            float v3 = acc[mt][nt][3] + bb.y;
            if (reluU) {
                v0 = fmaxf(v0, 0.f); v1 = fmaxf(v1, 0.f);
                v2 = fmaxf(v2, 0.f); v3 = fmaxf(v3, 0.f);
            }
            *(__half2*)(CU + (size_t)row * 512 + col)       = __floats2half2_rn(v0, v1);
            *(__half2*)(CU + (size_t)(row + 8) * 512 + col) = __floats2half2_rn(v2, v3);
        }
    }
#undef FILL
}

// ---------------------------------------------------------------------------
// FP16 tensor-core causal attention per (b,n,h): T=64, D=64. 128 thr, 4 warps.
// Masked BEFORE scaling: masked logit = -32767/8.
// ---------------------------------------------------------------------------
__global__ __launch_bounds__(128)
void attn_fp16(const __half* __restrict__ qf, const __half* __restrict__ kf,
               const __half* __restrict__ vf, __half* __restrict__ of)
{
    __shared__ __align__(128) unsigned char sm[3 * 8192];
    const uint32_t sb = smem_u32(sm);
    const uint32_t sQ = sb, sK = sb + 8192, sV = sb + 16384;

    const int idx = blockIdx.x;
    const int h = idx & 7;
    const int n = (idx >> 3) & 255;
    const int b = idx >> 11;
    const size_t base = ((size_t)(b * T_) * N_ + n) * FEAT + h * D_;
    const int tid = threadIdx.x;
    const size_t tstride = (size_t)N_ * FEAT;

#define LOADM(ptr, moff)                                                      \
    _Pragma("unroll")                                                         \
    for (int i = 0; i < 4; i++) {                                             \
        int lin = tid + i * 128;                                              \
        int t_ = lin >> 3, q_ = lin & 7;                                      \
        cp16(sb + (moff) + t_ * 128 + ((q_ ^ (t_ & 7)) << 4),                 \
             (ptr) + base + (size_t)t_ * tstride + q_ * 8);                   \
    }
    LOADM(qf, 0);
    LOADM(kf, 8192);
    LOADM(vf, 16384);
#undef LOADM
    asm volatile("cp.async.commit_group;");
    asm volatile("cp.async.wait_group 0;");
    __syncthreads();

    const int w = tid >> 5;
    const int lane = tid & 31;
    const int m0 = w * 16;
    const float NEG8 = -4095.875f;

    // ---- QK^T ----
    uint32_t aq[4][4];
    {
        int r = m0 + (lane & 7) + ((lane >> 3) & 1) * 8;
        int qc = lane >> 4;
#pragma unroll
        for (int ks = 0; ks < 4; ks++)
            ldsm4(sQ + r * 128 + (((ks * 2 + qc) ^ (r & 7)) << 4), aq[ks]);
    }

    float acc[8][4];
#pragma unroll
    for (int i = 0; i < 8; i++)
#pragma unroll
        for (int j = 0; j < 4; j++) acc[i][j] = 0.f;

    {
        int rn = (lane & 7) + ((lane >> 4) & 1) * 8;
        int kc = (lane >> 3) & 1;
#pragma unroll
        for (int ks = 0; ks < 4; ks++) {
#pragma unroll
            for (int p = 0; p < 4; p++) {
                int rt = p * 16 + rn;
                uint32_t bk[4];
                ldsm4(sK + rt * 128 + (((ks * 2 + kc) ^ (rt & 7)) << 4), bk);
                mma_fp16(acc[2 * p],     aq[ks], bk[0], bk[1]);
                mma_fp16(acc[2 * p + 1], aq[ks], bk[2], bk[3]);
            }
        }
    }

    // ---- softmax (mask before scale) ----
    const int colb = (lane & 3) * 2;
    const int r0 = m0 + (lane >> 2), r1 = r0 + 8;
    float m0v = NEG8, m1v = NEG8;
#pragma unroll
    for (int nt = 0; nt < 8; nt++) {
        int c = nt * 8 + colb;
        acc[nt][0] = (c     <= r0) ? acc[nt][0] * 0.125f : NEG8;
        acc[nt][1] = (c + 1 <= r0) ? acc[nt][1] * 0.125f : NEG8;
        acc[nt][2] = (c     <= r1) ? acc[nt][2] * 0.125f : NEG8;
        acc[nt][3] = (c + 1 <= r1) ? acc[nt][3] * 0.125f : NEG8;
        m0v = fmaxf(m0v, fmaxf(acc[nt][0], acc[nt][1]));
        m1v = fmaxf(m1v, fmaxf(acc[nt][2], acc[nt][3]));
    }
    m0v = fmaxf(m0v, __shfl_xor_sync(0xffffffffu, m0v, 1));
    m0v = fmaxf(m0v, __shfl_xor_sync(0xffffffffu, m0v, 2));
    m1v = fmaxf(m1v, __shfl_xor_sync(0xffffffffu, m1v, 1));
    m1v = fmaxf(m1v, __shfl_xor_sync(0xffffffffu, m1v, 2));

    float sum0 = 0.f, sum1 = 0.f;
#pragma unroll
    for (int nt = 0; nt < 8; nt++) {
        acc[nt][0] = __expf(acc[nt][0] - m0v);
        acc[nt][1] = __expf(acc[nt][1] - m0v);
        acc[nt][2] = __expf(acc[nt][2] - m1v);
        acc[nt][3] = __expf(acc[nt][3] - m1v);
        sum0 += acc[nt][0] + acc[nt][1];
        sum1 += acc[nt][2] + acc[nt][3];
    }
    sum0 += __shfl_xor_sync(0xffffffffu, sum0, 1);
    sum0 += __shfl_xor_sync(0xffffffffu, sum0, 2);
    sum1 += __shfl_xor_sync(0xffffffffu, sum1, 1);
    sum1 += __shfl_xor_sync(0xffffffffu, sum1, 2);
    const float inv0 = 1.f / sum0, inv1 = 1.f / sum1;

    // ---- write P (fp16) into this warp's own Q smem rows ----
#pragma unroll
    for (int nt = 0; nt < 8; nt++) {
        uint32_t o0 = r0 * 128 + ((nt ^ (r0 & 7)) << 4) + colb * 2;
        uint32_t o1 = r1 * 128 + ((nt ^ (r1 & 7)) << 4) + colb * 2;
        *(__half2*)(sm + o0) = __floats2half2_rn(acc[nt][0] * inv0, acc[nt][1] * inv0);
        *(__half2*)(sm + o1) = __floats2half2_rn(acc[nt][2] * inv1, acc[nt][3] * inv1);
    }
    __syncwarp();

    // ---- O = P V ----
    float accO[8][4];
#pragma unroll
    for (int i = 0; i < 8; i++)
#pragma unroll
        for (int j = 0; j < 4; j++) accO[i][j] = 0.f;

    {
        int rp = m0 + (lane & 7) + ((lane >> 3) & 1) * 8;
        int pqc = lane >> 4;
        int sv = lane & 15;
        int vqc = lane >> 4;
#pragma unroll
        for (int ks = 0; ks < 4; ks++) {
            uint32_t ap[4];
            ldsm4(sQ + rp * 128 + (((ks * 2 + pqc) ^ (rp & 7)) << 4), ap);
            int rv = ks * 16 + sv;
#pragma unroll
            for (int dt = 0; dt < 4; dt++) {
                uint32_t bv[4];
                ldsm4t(sV + rv * 128 + (((dt * 2 + vqc) ^ (rv & 7)) << 4), bv);
                mma_fp16(accO[2 * dt],     ap, bv[0], bv[1]);
                mma_fp16(accO[2 * dt + 1], ap, bv[2], bv[3]);
            }
        }
    }

    // ---- store O fp16 ----
#pragma unroll
    for (int nt = 0; nt < 8; nt++) {
        int col = nt * 8 + colb;
        *(__half2*)(of + base + (size_t)r0 * tstride + col) =
            __floats2half2_rn(accO[nt][0], accO[nt][1]);
        *(__half2*)(of + base + (size_t)r1 * tstride + col) =
            __floats2half2_rn(accO[nt][2], accO[nt][3]);
    }
}

// ---------------------------------------------------------------------------
// out = LayerNorm(a + b), both inputs fp16. Optional fp32 out, optional
// fp16 out. One warp per 512-dim row; 16B (8-half) chunks, 2 per thread.
// ---------------------------------------------------------------------------
__global__ __launch_bounds__(256)
void add_ln(const __half* __restrict__ a, const __half* __restrict__ b,
            float* __restrict__ out, __half2* __restrict__ oh)
{
    int row = blockIdx.x * 8 + (threadIdx.x >> 5);
    int l = threadIdx.x & 31;
    const uint4* pa = (const uint4*)(a + (size_t)row * 512);
    const uint4* pb = (const uint4*)(b + (size_t)row * 512);

    float x[16];
    float s = 0.f;
#pragma unroll
    for (int i = 0; i < 2; i++) {
        uint4 ua = pa[l + i * 32];
        uint4 ub = pb[l + i * 32];
        const __half2* ha = (const __half2*)&ua;
        const __half2* hb = (const __half2*)&ub;
#pragma unroll
        for (int j = 0; j < 4; j++) {
            float2 fa = __half22float2(ha[j]);
            float2 fb = __half22float2(hb[j]);
            float v0 = fa.x + fb.x, v1 = fa.y + fb.y;
            x[i * 8 + 2 * j]     = v0;
            x[i * 8 + 2 * j + 1] = v1;
            s += v0 + v1;
        }
    }
#pragma unroll
    for (int o = 16; o; o >>= 1) s += __shfl_xor_sync(0xffffffffu, s, o);
    float mean = s * (1.f / 512.f);

    float vs = 0.f;
#pragma unroll
    for (int k = 0; k < 16; k++) {
        float d = x[k] - mean;
        vs += d * d;
    }
#pragma unroll
    for (int o = 16; o; o >>= 1) vs += __shfl_xor_sync(0xffffffffu, vs, o);
    float invstd = rsqrtf(vs * (1.f / 512.f) + 1e-5f);

#pragma unroll
    for (int i = 0; i < 2; i++) {
        int c0 = (l + i * 32) * 8;
        float y[8];
#pragma unroll
        for (int j = 0; j < 8; j++) y[j] = (x[i * 8 + j] - mean) * invstd;
        if (out) {
            float* po = out + (size_t)row * 512 + c0;
            *(float4*)(po)     = make_float4(y[0], y[1], y[2], y[3]);
            *(float4*)(po + 4) = make_float4(y[4], y[5], y[6], y[7]);
        }
        if (oh) {
            __half2* ph = oh + (row * 512 + c0) / 2;
            ph[0] = __floats2half2_rn(y[0], y[1]);
            ph[1] = __floats2half2_rn(y[2], y[3]);
            ph[2] = __floats2half2_rn(y[4], y[5]);
            ph[3] = __floats2half2_rn(y[6], y[7]);
        }
    }
}

// ---------------------------------------------------------------------------
// Launch pipeline (graph-capturable: launches only)
// ---------------------------------------------------------------------------
extern "C" void kernel_launch(void* const* d_in, const int* in_sizes, int n_in,
                              void* d_out, int out_size)
{
    const float* xl = (const float*)d_in[0];
    const float* xh = (const float*)d_in[1];
    const float* te = (const float*)d_in[2];
    const float* Wq = (const float*)d_in[3];
    const float* bq = (const float*)d_in[4];
    const float* Wk = (const float*)d_in[5];
    const float* bk = (const float*)d_in[6];
    const float* Wv = (const float*)d_in[7];
    const float* bv = (const float*)d_in[8];
    const float* Wo = (const float*)d_in[9];
    const float* bo = (const float*)d_in[10];
    const float* W1 = (const float*)d_in[11];
    const float* b1 = (const float*)d_in[12];
    const float* W2 = (const float*)d_in[13];
    const float* b2 = (const float*)d_in[14];
    float* out = (float*)d_out;

    __half *hf, *wt;
    cudaGetSymbolAddress((void**)&hf, g_hf);
    cudaGetSymbolAddress((void**)&wt, g_wt);

    __half* s0f = hf + 0ull * ELEMS;
    __half* s1f = hf + 1ull * ELEMS;
    __half* qf  = hf + 2ull * ELEMS;
    __half* kf  = hf + 3ull * ELEMS;
    __half* vf  = hf + 4ull * ELEMS;
    __half* aof = hf + 5ull * ELEMS;
    __half* wof = hf + 6ull * ELEMS;
    __half* vaf = hf + 7ull * ELEMS;
    __half* f1f = hf + 8ull * ELEMS;
    __half* f2f = hf + 9ull * ELEMS;

    cudaFuncSetAttribute(gemm_fp16, cudaFuncAttributeMaxDynamicSharedMemorySize, 65536);

    const dim3 gg(4, 1024);
    const dim3 gqkv(12, 1024);
    const int nadd = ELEMS / 4 / 256;

    // 0: weight transpose (fp16 K-major)
    prep_w<<<dim3(16, 16, 6), dim3(32, 8)>>>(Wq, Wk, Wv, Wo, W1, W2, wt);
    // 1: fused residual adds -> fp16
    add_te01<<<nadd, 256>>>((const float4*)xl, (const float4*)xh, (const float4*)te,
                            (__half2*)s0f, (__half2*)s1f);
    // 2: fused Q+K+V projection -> fp16
    gemm_fp16<<<gqkv, 128, 65536>>>(s0f, s1f,
                                    wt + 0 * WSZ, bq, qf, 0,
                                    wt + 1 * WSZ, bk, kf, 1,
                                    wt + 2 * WSZ, bv, vf, 1);
    // 3: tensor-core attention -> fp16
    attn_fp16<<<B_ * N_ * H_, 128>>>(qf, kf, vf, aof);
    // 4: Wo projection -> wof fp16
    gemm_fp16<<<gg, 128, 65536>>>(aof, 0,
                                  wt + 3 * WSZ, bo, wof, 0,
                                  0, 0, 0, 0,
                                  0, 0, 0, 0);
    // 5: val = LN(wof + s0f) -> vaf fp16
    add_ln<<<TOKENS / 8, 256>>>(wof, s0f, 0, (__half2*)vaf);
    // 6: ff1 = relu(val @ W1 + b1) -> f1f fp16
    gemm_fp16<<<gg, 128, 65536>>>(vaf, 0,
                                  wt + 4 * WSZ, b1, f1f, 1,
                                  0, 0, 0, 0,
                                  0, 0, 0, 0);
    // 7: ff2 = ff1 @ W2 + b2 -> f2f fp16
    gemm_fp16<<<gg, 128, 65536>>>(f1f, 0,
                                  wt + 5 * WSZ, b2, f2f, 0,
                                  0, 0, 0, 0,
                                  0, 0, 0, 0);
    // 8: out = LN(f2f + vaf) -> fp32
    add_ln<<<TOKENS / 8, 256>>>(f2f, vaf, out, 0);
}

// round 15
// speedup vs baseline: 1.3631x; 1.3631x over previous
#include <cuda_runtime.h>
#include <cuda_fp16.h>
#include <math.h>
#include <stdint.h>

#define B_ 8
#define T_ 64
#define N_ 256
#define H_ 8
#define D_ 64
#define FEAT 512
#define TOKENS (B_*T_*N_)          /* 131072 */
#define ELEMS  (TOKENS*FEAT)       /* 67108864 */
#define WSZ    (512*512)

// ---------------------------------------------------------------------------
// Scratch (device globals — no cudaMalloc allowed). All-fp16 intermediates.
// ---------------------------------------------------------------------------
__device__ __half g_hf[10ull * ELEMS];
__device__ __half g_wt[6 * WSZ];      // K-major fp16 weights

// ---------------------------------------------------------------------------
// Helpers
// ---------------------------------------------------------------------------
__device__ __forceinline__ uint32_t smem_u32(const void* p) {
    uint32_t a;
    asm("{ .reg .u64 t; cvta.to.shared.u64 t, %1; cvt.u32.u64 %0, t; }" : "=r"(a) : "l"(p));
    return a;
}

__device__ __forceinline__ void cp16(uint32_t dst, const void* src) {
    asm volatile("cp.async.cg.shared.global [%0], [%1], 16;"
                 :: "r"(dst), "l"(__cvta_generic_to_global(src)));
}

__device__ __forceinline__ void ldsm4(uint32_t addr, uint32_t* r) {
    asm volatile("ldmatrix.sync.aligned.m8n8.x4.shared.b16 {%0,%1,%2,%3}, [%4];"
                 : "=r"(r[0]), "=r"(r[1]), "=r"(r[2]), "=r"(r[3]) : "r"(addr));
}

__device__ __forceinline__ void ldsm4t(uint32_t addr, uint32_t* r) {
    asm volatile("ldmatrix.sync.aligned.m8n8.x4.trans.shared.b16 {%0,%1,%2,%3}, [%4];"
                 : "=r"(r[0]), "=r"(r[1]), "=r"(r[2]), "=r"(r[3]) : "r"(addr));
}

__device__ __forceinline__ void mma_fp16(float* d, const uint32_t* a,
                                         uint32_t b0, uint32_t b1) {
    asm volatile(
        "mma.sync.aligned.m16n8k16.row.col.f32.f16.f16.f32 "
        "{%0,%1,%2,%3}, {%4,%5,%6,%7}, {%8,%9}, {%0,%1,%2,%3};"
        : "+f"(d[0]), "+f"(d[1]), "+f"(d[2]), "+f"(d[3])
        : "r"(a[0]), "r"(a[1]), "r"(a[2]), "r"(a[3]), "r"(b0), "r"(b1));
}

// ---------------------------------------------------------------------------
// Weight prep: transpose to K-major fp16. Wt[z][n][k] = fp16(W_z[k][n]).
// ---------------------------------------------------------------------------
__global__ __launch_bounds__(256)
void prep_w(const float* W0, const float* W1, const float* W2,
            const float* W3, const float* W4, const float* W5,
            __half* __restrict__ Wt)
{
    const float* Ws[6] = {W0, W1, W2, W3, W4, W5};
    const float* W = Ws[blockIdx.z];
    __shared__ float t[32][33];
    int bx = blockIdx.x * 32, by = blockIdx.y * 32;
#pragma unroll
    for (int r = 0; r < 32; r += 8)
        t[threadIdx.y + r][threadIdx.x] =
            W[(size_t)(by + threadIdx.y + r) * 512 + bx + threadIdx.x];
    __syncthreads();
    size_t base = (size_t)blockIdx.z * WSZ;
#pragma unroll
    for (int r = 0; r < 32; r += 8)
        Wt[base + (size_t)(bx + threadIdx.y + r) * 512 + by + threadIdx.x] =
            __float2half_rn(t[threadIdx.x][threadIdx.y + r]);
}

// ---------------------------------------------------------------------------
// Fused residual adds: s0 = fp16(xl+te), s1 = fp16(xh+te).
// ---------------------------------------------------------------------------
__global__ __launch_bounds__(256)
void add_te01(const float4* __restrict__ xl, const float4* __restrict__ xh,
              const float4* __restrict__ te,
              __half2* __restrict__ o0, __half2* __restrict__ o1)
{
    int i = blockIdx.x * 256 + threadIdx.x;
    float4 t = te[i];
    float4 a = xl[i];
    float4 b = xh[i];
    o0[2 * i]     = __floats2half2_rn(a.x + t.x, a.y + t.y);
    o0[2 * i + 1] = __floats2half2_rn(a.z + t.z, a.w + t.w);
    o1[2 * i]     = __floats2half2_rn(b.x + t.x, b.y + t.y);
    o1[2 * i + 1] = __floats2half2_rn(b.z + t.z, b.w + t.w);
}

// ---------------------------------------------------------------------------
// FP16 tensor-core GEMM (R13-proven config): single pass, K-chunk 32,
// 2-stage cp.async, CTA 128x128, 128 thr, 4 warps (64x64). Triple operand
// set via blockIdx.x>>2 (fused Q+K+V). Output fp16 (+bias, optional relu).
// ---------------------------------------------------------------------------
__global__ __launch_bounds__(128, 2)
void gemm_fp16(const __half* __restrict__ A0, const __half* __restrict__ A1,
               const __half* B0, const float* bias0, __half* C0, int relu0,
               const __half* B1, const float* bias1, __half* C1, int relu1,
               const __half* B2, const float* bias2, __half* C2, int relu2)
{
    extern __shared__ __align__(128) unsigned char smem[];
    const uint32_t sb = smem_u32(smem);

    const int tid  = threadIdx.x;
    const int lane = tid & 31;
    const int warp = tid >> 5;
    const int wm = warp >> 1, wn = warp & 1;
    const int m0 = blockIdx.y * 128;

    const int set = blockIdx.x >> 2;
    const int n0  = (blockIdx.x & 3) * 128;

    const __half* AU = (set == 0) ? A0 : A1;
    const __half* BU = (set == 0) ? B0 : ((set == 1) ? B1 : B2);
    const float* biasU = (set == 0) ? bias0 : ((set == 1) ? bias1 : bias2);
    __half* CU = (set == 0) ? C0 : ((set == 1) ? C1 : C2);
    const int reluU = (set == 0) ? relu0 : ((set == 1) ? relu1 : relu2);

    const __half* Ag = AU + (size_t)m0 * 512;
    const __half* Bg = BU + (size_t)n0 * 512;

    int frow[4], fc[4];
    uint32_t foff[4];
#pragma unroll
    for (int j = 0; j < 4; j++) {
        int lin = tid + j * 128;
        frow[j] = lin >> 2;
        fc[j]   = lin & 3;
        foff[j] = frow[j] * 64 + ((uint32_t)(fc[j] ^ ((frow[j] >> 1) & 3)) << 4);
    }

#define FILL(kc, st)                                                          \
    do {                                                                      \
        uint32_t s_ = sb + (st) * 16384;                                      \
        _Pragma("unroll")                                                     \
        for (int j = 0; j < 4; j++) {                                         \
            size_t g_ = (size_t)frow[j] * 512 + (kc) * 32 + fc[j] * 8;        \
            cp16(s_ + foff[j],         Ag + g_);                              \
            cp16(s_ + 8192 + foff[j],  Bg + g_);                              \
        }                                                                     \
        asm volatile("cp.async.commit_group;");                               \
    } while (0)

    float acc[4][8][4];
#pragma unroll
    for (int i = 0; i < 4; i++)
#pragma unroll
        for (int j = 0; j < 8; j++)
#pragma unroll
            for (int k = 0; k < 4; k++) acc[i][j][k] = 0.f;

    const int rA_base = wm * 64 + (lane & 7) + ((lane >> 3) & 1) * 8;
    const uint32_t kbA = ((lane >> 4) & 1) * 16;
    const int rB_base = wn * 64 + (lane & 7) + ((lane >> 4) & 1) * 8;
    const uint32_t kbB = ((lane >> 3) & 1) * 16;

    FILL(0, 0);
    FILL(1, 1);

    for (int c = 0; c < 16; c++) {
        if (c < 15) asm volatile("cp.async.wait_group 1;");
        else        asm volatile("cp.async.wait_group 0;");
        __syncthreads();

        const uint32_t sA = sb + (c & 1) * 16384;
        const uint32_t sB = sA + 8192;

#pragma unroll
        for (int ks = 0; ks < 2; ks++) {
            uint32_t ah[4][4], bh[4][4];
#pragma unroll
            for (int mt = 0; mt < 4; mt++) {
                int r = rA_base + mt * 16;
                uint32_t kb = kbA + ks * 32;
                ldsm4(sA + r * 64 + (kb ^ (((r >> 1) & 3) << 4)), ah[mt]);
            }
#pragma unroll
            for (int p = 0; p < 4; p++) {
                int r = rB_base + p * 16;
                uint32_t kb = kbB + ks * 32;
                ldsm4(sB + r * 64 + (kb ^ (((r >> 1) & 3) << 4)), bh[p]);
            }
#pragma unroll
            for (int mt = 0; mt < 4; mt++)
#pragma unroll
                for (int p = 0; p < 4; p++) {
                    mma_fp16(acc[mt][2 * p],     ah[mt], bh[p][0], bh[p][1]);
                    mma_fp16(acc[mt][2 * p + 1], ah[mt], bh[p][2], bh[p][3]);
                }
        }
        __syncthreads();
        if (c + 2 < 16) FILL(c + 2, (c & 1));
    }

    // ---- epilogue: bias (+relu), fp16 stores ----
#pragma unroll
    for (int mt = 0; mt < 4; mt++) {
        int row = m0 + wm * 64 + mt * 16 + (lane >> 2);
#pragma unroll
        for (int nt = 0; nt < 8; nt++) {
            int col = n0 + wn * 64 + nt * 8 + (lane & 3) * 2;
            float2 bb = __ldg((const float2*)(biasU + col));
            float v0 = acc[mt][nt][0] + bb.x;
            float v1 = acc[mt][nt][1] + bb.y;
            float v2 = acc[mt][nt][2] + bb.x;
            float v3 = acc[mt][nt][3] + bb.y;
            if (reluU) {
                v0 = fmaxf(v0, 0.f); v1 = fmaxf(v1, 0.f);
                v2 = fmaxf(v2, 0.f); v3 = fmaxf(v3, 0.f);
            }
            *(__half2*)(CU + (size_t)row * 512 + col)       = __floats2half2_rn(v0, v1);
            *(__half2*)(CU + (size_t)(row + 8) * 512 + col) = __floats2half2_rn(v2, v3);
        }
    }
#undef FILL
}

// ---------------------------------------------------------------------------
// FP16 tensor-core causal attention per (b,n,h): T=64, D=64. 128 thr, 4 warps.
// Split-wait: Q+K in group 0, V in group 1; V-wait deferred past softmax.
// Masked BEFORE scaling: masked logit = -32767/8.
// ---------------------------------------------------------------------------
__global__ __launch_bounds__(128)
void attn_fp16(const __half* __restrict__ qf, const __half* __restrict__ kf,
               const __half* __restrict__ vf, __half* __restrict__ of)
{
    __shared__ __align__(128) unsigned char sm[3 * 8192];
    const uint32_t sb = smem_u32(sm);
    const uint32_t sQ = sb, sK = sb + 8192, sV = sb + 16384;

    const int idx = blockIdx.x;
    const int h = idx & 7;
    const int n = (idx >> 3) & 255;
    const int b = idx >> 11;
    const size_t base = ((size_t)(b * T_) * N_ + n) * FEAT + h * D_;
    const int tid = threadIdx.x;
    const size_t tstride = (size_t)N_ * FEAT;

#define LOADM(ptr, moff)                                                      \
    _Pragma("unroll")                                                         \
    for (int i = 0; i < 4; i++) {                                             \
        int lin = tid + i * 128;                                              \
        int t_ = lin >> 3, q_ = lin & 7;                                      \
        cp16(sb + (moff) + t_ * 128 + ((q_ ^ (t_ & 7)) << 4),                 \
             (ptr) + base + (size_t)t_ * tstride + q_ * 8);                   \
    }
    LOADM(qf, 0);
    LOADM(kf, 8192);
    asm volatile("cp.async.commit_group;");
    LOADM(vf, 16384);
    asm volatile("cp.async.commit_group;");
#undef LOADM
    // wait for Q+K only; V arrives during QK/softmax
    asm volatile("cp.async.wait_group 1;");
    __syncthreads();

    const int w = tid >> 5;
    const int lane = tid & 31;
    const int m0 = w * 16;
    const float NEG8 = -4095.875f;

    // ---- QK^T ----
    uint32_t aq[4][4];
    {
        int r = m0 + (lane & 7) + ((lane >> 3) & 1) * 8;
        int qc = lane >> 4;
#pragma unroll
        for (int ks = 0; ks < 4; ks++)
            ldsm4(sQ + r * 128 + (((ks * 2 + qc) ^ (r & 7)) << 4), aq[ks]);
    }

    float acc[8][4];
#pragma unroll
    for (int i = 0; i < 8; i++)
#pragma unroll
        for (int j = 0; j < 4; j++) acc[i][j] = 0.f;

    {
        int rn = (lane & 7) + ((lane >> 4) & 1) * 8;
        int kc = (lane >> 3) & 1;
#pragma unroll
        for (int ks = 0; ks < 4; ks++) {
#pragma unroll
            for (int p = 0; p < 4; p++) {
                int rt = p * 16 + rn;
                uint32_t bk[4];
                ldsm4(sK + rt * 128 + (((ks * 2 + kc) ^ (rt & 7)) << 4), bk);
                mma_fp16(acc[2 * p],     aq[ks], bk[0], bk[1]);
                mma_fp16(acc[2 * p + 1], aq[ks], bk[2], bk[3]);
            }
        }
    }

    // ---- softmax (mask before scale) ----
    const int colb = (lane & 3) * 2;
    const int r0 = m0 + (lane >> 2), r1 = r0 + 8;
    float m0v = NEG8, m1v = NEG8;
#pragma unroll
    for (int nt = 0; nt < 8; nt++) {
        int c = nt * 8 + colb;
        acc[nt][0] = (c     <= r0) ? acc[nt][0] * 0.125f : NEG8;
        acc[nt][1] = (c + 1 <= r0) ? acc[nt][1] * 0.125f : NEG8;
        acc[nt][2] = (c     <= r1) ? acc[nt][2] * 0.125f : NEG8;
        acc[nt][3] = (c + 1 <= r1) ? acc[nt][3] * 0.125f : NEG8;
        m0v = fmaxf(m0v, fmaxf(acc[nt][0], acc[nt][1]));
        m1v = fmaxf(m1v, fmaxf(acc[nt][2], acc[nt][3]));
    }
    m0v = fmaxf(m0v, __shfl_xor_sync(0xffffffffu, m0v, 1));
    m0v = fmaxf(m0v, __shfl_xor_sync(0xffffffffu, m0v, 2));
    m1v = fmaxf(m1v, __shfl_xor_sync(0xffffffffu, m1v, 1));
    m1v = fmaxf(m1v, __shfl_xor_sync(0xffffffffu, m1v, 2));

    float sum0 = 0.f, sum1 = 0.f;
#pragma unroll
    for (int nt = 0; nt < 8; nt++) {
        acc[nt][0] = __expf(acc[nt][0] - m0v);
        acc[nt][1] = __expf(acc[nt][1] - m0v);
        acc[nt][2] = __expf(acc[nt][2] - m1v);
        acc[nt][3] = __expf(acc[nt][3] - m1v);
        sum0 += acc[nt][0] + acc[nt][1];
        sum1 += acc[nt][2] + acc[nt][3];
    }
    sum0 += __shfl_xor_sync(0xffffffffu, sum0, 1);
    sum0 += __shfl_xor_sync(0xffffffffu, sum0, 2);
    sum1 += __shfl_xor_sync(0xffffffffu, sum1, 1);
    sum1 += __shfl_xor_sync(0xffffffffu, sum1, 2);
    const float inv0 = 1.f / sum0, inv1 = 1.f / sum1;

    // ---- write P (fp16) into this warp's own Q smem rows ----
#pragma unroll
    for (int nt = 0; nt < 8; nt++) {
        uint32_t o0 = r0 * 128 + ((nt ^ (r0 & 7)) << 4) + colb * 2;
        uint32_t o1 = r1 * 128 + ((nt ^ (r1 & 7)) << 4) + colb * 2;
        *(__half2*)(sm + o0) = __floats2half2_rn(acc[nt][0] * inv0, acc[nt][1] * inv0);
        *(__half2*)(sm + o1) = __floats2half2_rn(acc[nt][2] * inv1, acc[nt][3] * inv1);
    }
    // now ensure V has landed (group 0 remaining) before PV reads it
    asm volatile("cp.async.wait_group 0;");
    __syncwarp();

    // ---- O = P V ----
    float accO[8][4];
#pragma unroll
    for (int i = 0; i < 8; i++)
#pragma unroll
        for (int j = 0; j < 4; j++) accO[i][j] = 0.f;

    {
        int rp = m0 + (lane & 7) + ((lane >> 3) & 1) * 8;
        int pqc = lane >> 4;
        int sv = lane & 15;
        int vqc = lane >> 4;
#pragma unroll
        for (int ks = 0; ks < 4; ks++) {
            uint32_t ap[4];
            ldsm4(sQ + rp * 128 + (((ks * 2 + pqc) ^ (rp & 7)) << 4), ap);
            int rv = ks * 16 + sv;
#pragma unroll
            for (int dt = 0; dt < 4; dt++) {
                uint32_t bv[4];
                ldsm4t(sV + rv * 128 + (((dt * 2 + vqc) ^ (rv & 7)) << 4), bv);
                mma_fp16(accO[2 * dt],     ap, bv[0], bv[1]);
                mma_fp16(accO[2 * dt + 1], ap, bv[2], bv[3]);
            }
        }
    }

    // ---- store O fp16 ----
#pragma unroll
    for (int nt = 0; nt < 8; nt++) {
        int col = nt * 8 + colb;
        *(__half2*)(of + base + (size_t)r0 * tstride + col) =
            __floats2half2_rn(accO[nt][0], accO[nt][1]);
        *(__half2*)(of + base + (size_t)r1 * tstride + col) =
            __floats2half2_rn(accO[nt][2], accO[nt][3]);
    }
}

// ---------------------------------------------------------------------------
// out = LayerNorm(a + b), both inputs fp16. Optional fp32 out, optional
// fp16 out. One warp per 512-dim row; 16B (8-half) chunks, 2 per thread.
// ---------------------------------------------------------------------------
__global__ __launch_bounds__(256)
void add_ln(const __half* __restrict__ a, const __half* __restrict__ b,
            float* __restrict__ out, __half2* __restrict__ oh)
{
    int row = blockIdx.x * 8 + (threadIdx.x >> 5);
    int l = threadIdx.x & 31;
    const uint4* pa = (const uint4*)(a + (size_t)row * 512);
    const uint4* pb = (const uint4*)(b + (size_t)row * 512);

    float x[16];
    float s = 0.f;
#pragma unroll
    for (int i = 0; i < 2; i++) {
        uint4 ua = pa[l + i * 32];
        uint4 ub = pb[l + i * 32];
        const __half2* ha = (const __half2*)&ua;
        const __half2* hb = (const __half2*)&ub;
#pragma unroll
        for (int j = 0; j < 4; j++) {
            float2 fa = __half22float2(ha[j]);
            float2 fb = __half22float2(hb[j]);
            float v0 = fa.x + fb.x, v1 = fa.y + fb.y;
            x[i * 8 + 2 * j]     = v0;
            x[i * 8 + 2 * j + 1] = v1;
            s += v0 + v1;
        }
    }
#pragma unroll
    for (int o = 16; o; o >>= 1) s += __shfl_xor_sync(0xffffffffu, s, o);
    float mean = s * (1.f / 512.f);

    float vs = 0.f;
#pragma unroll
    for (int k = 0; k < 16; k++) {
        float d = x[k] - mean;
        vs += d * d;
    }
#pragma unroll
    for (int o = 16; o; o >>= 1) vs += __shfl_xor_sync(0xffffffffu, vs, o);
    float invstd = rsqrtf(vs * (1.f / 512.f) + 1e-5f);

#pragma unroll
    for (int i = 0; i < 2; i++) {
        int c0 = (l + i * 32) * 8;
        float y[8];
#pragma unroll
        for (int j = 0; j < 8; j++) y[j] = (x[i * 8 + j] - mean) * invstd;
        if (out) {
            float* po = out + (size_t)row * 512 + c0;
            *(float4*)(po)     = make_float4(y[0], y[1], y[2], y[3]);
            *(float4*)(po + 4) = make_float4(y[4], y[5], y[6], y[7]);
        }
        if (oh) {
            __half2* ph = oh + (row * 512 + c0) / 2;
            ph[0] = __floats2half2_rn(y[0], y[1]);
            ph[1] = __floats2half2_rn(y[2], y[3]);
            ph[2] = __floats2half2_rn(y[4], y[5]);
            ph[3] = __floats2half2_rn(y[6], y[7]);
        }
    }
}

// ---------------------------------------------------------------------------
// Launch pipeline (graph-capturable: launches only)
// ---------------------------------------------------------------------------
extern "C" void kernel_launch(void* const* d_in, const int* in_sizes, int n_in,
                              void* d_out, int out_size)
{
    const float* xl = (const float*)d_in[0];
    const float* xh = (const float*)d_in[1];
    const float* te = (const float*)d_in[2];
    const float* Wq = (const float*)d_in[3];
    const float* bq = (const float*)d_in[4];
    const float* Wk = (const float*)d_in[5];
    const float* bk = (const float*)d_in[6];
    const float* Wv = (const float*)d_in[7];
    const float* bv = (const float*)d_in[8];
    const float* Wo = (const float*)d_in[9];
    const float* bo = (const float*)d_in[10];
    const float* W1 = (const float*)d_in[11];
    const float* b1 = (const float*)d_in[12];
    const float* W2 = (const float*)d_in[13];
    const float* b2 = (const float*)d_in[14];
    float* out = (float*)d_out;

    __half *hf, *wt;
    cudaGetSymbolAddress((void**)&hf, g_hf);
    cudaGetSymbolAddress((void**)&wt, g_wt);

    __half* s0f = hf + 0ull * ELEMS;
    __half* s1f = hf + 1ull * ELEMS;
    __half* qf  = hf + 2ull * ELEMS;
    __half* kf  = hf + 3ull * ELEMS;
    __half* vf  = hf + 4ull * ELEMS;
    __half* aof = hf + 5ull * ELEMS;
    __half* wof = hf + 6ull * ELEMS;
    __half* vaf = hf + 7ull * ELEMS;
    __half* f1f = hf + 8ull * ELEMS;
    __half* f2f = hf + 9ull * ELEMS;

    cudaFuncSetAttribute(gemm_fp16, cudaFuncAttributeMaxDynamicSharedMemorySize, 32768);

    const dim3 gg(4, 1024);
    const dim3 gqkv(12, 1024);
    const int nadd = ELEMS / 4 / 256;

    // 0: weight transpose (fp16 K-major)
    prep_w<<<dim3(16, 16, 6), dim3(32, 8)>>>(Wq, Wk, Wv, Wo, W1, W2, wt);
    // 1: fused residual adds -> fp16
    add_te01<<<nadd, 256>>>((const float4*)xl, (const float4*)xh, (const float4*)te,
                            (__half2*)s0f, (__half2*)s1f);
    // 2: fused Q+K+V projection -> fp16
    gemm_fp16<<<gqkv, 128, 32768>>>(s0f, s1f,
                                    wt + 0 * WSZ, bq, qf, 0,
                                    wt + 1 * WSZ, bk, kf, 1,
                                    wt + 2 * WSZ, bv, vf, 1);
    // 3: tensor-core attention -> fp16
    attn_fp16<<<B_ * N_ * H_, 128>>>(qf, kf, vf, aof);
    // 4: Wo projection -> wof fp16
    gemm_fp16<<<gg, 128, 32768>>>(aof, 0,
                                  wt + 3 * WSZ, bo, wof, 0,
                                  0, 0, 0, 0,
                                  0, 0, 0, 0);
    // 5: val = LN(wof + s0f) -> vaf fp16
    add_ln<<<TOKENS / 8, 256>>>(wof, s0f, 0, (__half2*)vaf);
    // 6: ff1 = relu(val @ W1 + b1) -> f1f fp16
    gemm_fp16<<<gg, 128, 32768>>>(vaf, 0,
                                  wt + 4 * WSZ, b1, f1f, 1,
                                  0, 0, 0, 0,
                                  0, 0, 0, 0);
    // 7: ff2 = ff1 @ W2 + b2 -> f2f fp16
    gemm_fp16<<<gg, 128, 32768>>>(f1f, 0,
                                  wt + 5 * WSZ, b2, f2f, 0,
                                  0, 0, 0, 0,
                                  0, 0, 0, 0);
    // 8: out = LN(f2f + vaf) -> fp32
    add_ln<<<TOKENS / 8, 256>>>(f2f, vaf, out, 0);
}

// round 16
// speedup vs baseline: 1.3924x; 1.0215x over previous
#include <cuda_runtime.h>
#include <cuda_fp16.h>
#include <math.h>
#include <stdint.h>

#define B_ 8
#define T_ 64
#define N_ 256
#define H_ 8
#define D_ 64
#define FEAT 512
#define TOKENS (B_*T_*N_)          /* 131072 */
#define ELEMS  (TOKENS*FEAT)       /* 67108864 */
#define WSZ    (512*512)

// ---------------------------------------------------------------------------
// Scratch (device globals — no cudaMalloc allowed). All-fp16 intermediates.
// ---------------------------------------------------------------------------
__device__ __half g_hf[10ull * ELEMS];
__device__ __half g_wt[6 * WSZ];      // K-major fp16 weights

// ---------------------------------------------------------------------------
// Helpers
// ---------------------------------------------------------------------------
__device__ __forceinline__ uint32_t smem_u32(const void* p) {
    uint32_t a;
    asm("{ .reg .u64 t; cvta.to.shared.u64 t, %1; cvt.u32.u64 %0, t; }" : "=r"(a) : "l"(p));
    return a;
}

__device__ __forceinline__ void cp16(uint32_t dst, const void* src) {
    asm volatile("cp.async.cg.shared.global [%0], [%1], 16;"
                 :: "r"(dst), "l"(__cvta_generic_to_global(src)));
}

__device__ __forceinline__ void ldsm4(uint32_t addr, uint32_t* r) {
    asm volatile("ldmatrix.sync.aligned.m8n8.x4.shared.b16 {%0,%1,%2,%3}, [%4];"
                 : "=r"(r[0]), "=r"(r[1]), "=r"(r[2]), "=r"(r[3]) : "r"(addr));
}

__device__ __forceinline__ void ldsm4t(uint32_t addr, uint32_t* r) {
    asm volatile("ldmatrix.sync.aligned.m8n8.x4.trans.shared.b16 {%0,%1,%2,%3}, [%4];"
                 : "=r"(r[0]), "=r"(r[1]), "=r"(r[2]), "=r"(r[3]) : "r"(addr));
}

__device__ __forceinline__ void mma_fp16(float* d, const uint32_t* a,
                                         uint32_t b0, uint32_t b1) {
    asm volatile(
        "mma.sync.aligned.m16n8k16.row.col.f32.f16.f16.f32 "
        "{%0,%1,%2,%3}, {%4,%5,%6,%7}, {%8,%9}, {%0,%1,%2,%3};"
        : "+f"(d[0]), "+f"(d[1]), "+f"(d[2]), "+f"(d[3])
        : "r"(a[0]), "r"(a[1]), "r"(a[2]), "r"(a[3]), "r"(b0), "r"(b1));
}

// ---------------------------------------------------------------------------
// No-op spacer so the fused QKV GEMM lands at launch index 3 (ncu target).
// ---------------------------------------------------------------------------
__global__ void nop_kernel() {}

// ---------------------------------------------------------------------------
// Weight prep: transpose to K-major fp16. Wt[z][n][k] = fp16(W_z[k][n]).
// ---------------------------------------------------------------------------
__global__ __launch_bounds__(256)
void prep_w(const float* W0, const float* W1, const float* W2,
            const float* W3, const float* W4, const float* W5,
            __half* __restrict__ Wt)
{
    const float* Ws[6] = {W0, W1, W2, W3, W4, W5};
    const float* W = Ws[blockIdx.z];
    __shared__ float t[32][33];
    int bx = blockIdx.x * 32, by = blockIdx.y * 32;
#pragma unroll
    for (int r = 0; r < 32; r += 8)
        t[threadIdx.y + r][threadIdx.x] =
            W[(size_t)(by + threadIdx.y + r) * 512 + bx + threadIdx.x];
    __syncthreads();
    size_t base = (size_t)blockIdx.z * WSZ;
#pragma unroll
    for (int r = 0; r < 32; r += 8)
        Wt[base + (size_t)(bx + threadIdx.y + r) * 512 + by + threadIdx.x] =
            __float2half_rn(t[threadIdx.x][threadIdx.y + r]);
}

// ---------------------------------------------------------------------------
// Fused residual adds: s0 = fp16(xl+te), s1 = fp16(xh+te).
// ---------------------------------------------------------------------------
__global__ __launch_bounds__(256)
void add_te01(const float4* __restrict__ xl, const float4* __restrict__ xh,
              const float4* __restrict__ te,
              __half2* __restrict__ o0, __half2* __restrict__ o1)
{
    int i = blockIdx.x * 256 + threadIdx.x;
    float4 t = te[i];
    float4 a = xl[i];
    float4 b = xh[i];
    o0[2 * i]     = __floats2half2_rn(a.x + t.x, a.y + t.y);
    o0[2 * i + 1] = __floats2half2_rn(a.z + t.z, a.w + t.w);
    o1[2 * i]     = __floats2half2_rn(b.x + t.x, b.y + t.y);
    o1[2 * i + 1] = __floats2half2_rn(b.z + t.z, b.w + t.w);
}

// ---------------------------------------------------------------------------
// FP16 tensor-core GEMM: single pass, K-chunk 32, 3-stage cp.async pipeline
// (16KB/stage, 48KB dynamic; 2 CTAs/SM). CTA 128x128, 128 thr, 4 warps
// (64x64). Triple operand set via blockIdx.x>>2 (fused Q+K+V).
// Output fp16 (+bias, optional relu).
// ---------------------------------------------------------------------------
__global__ __launch_bounds__(128, 2)
void gemm_fp16(const __half* __restrict__ A0, const __half* __restrict__ A1,
               const __half* B0, const float* bias0, __half* C0, int relu0,
               const __half* B1, const float* bias1, __half* C1, int relu1,
               const __half* B2, const float* bias2, __half* C2, int relu2)
{
    extern __shared__ __align__(128) unsigned char smem[];
    const uint32_t sb = smem_u32(smem);

    const int tid  = threadIdx.x;
    const int lane = tid & 31;
    const int warp = tid >> 5;
    const int wm = warp >> 1, wn = warp & 1;
    const int m0 = blockIdx.y * 128;

    const int set = blockIdx.x >> 2;
    const int n0  = (blockIdx.x & 3) * 128;

    const __half* AU = (set == 0) ? A0 : A1;
    const __half* BU = (set == 0) ? B0 : ((set == 1) ? B1 : B2);
    const float* biasU = (set == 0) ? bias0 : ((set == 1) ? bias1 : bias2);
    __half* CU = (set == 0) ? C0 : ((set == 1) ? C1 : C2);
    const int reluU = (set == 0) ? relu0 : ((set == 1) ? relu1 : relu2);

    const __half* Ag = AU + (size_t)m0 * 512;
    const __half* Bg = BU + (size_t)n0 * 512;

    int frow[4], fc[4];
    uint32_t foff[4];
#pragma unroll
    for (int j = 0; j < 4; j++) {
        int lin = tid + j * 128;
        frow[j] = lin >> 2;
        fc[j]   = lin & 3;
        foff[j] = frow[j] * 64 + ((uint32_t)(fc[j] ^ ((frow[j] >> 1) & 3)) << 4);
    }

#define FILL(kc, st)                                                          \
    do {                                                                      \
        uint32_t s_ = sb + (st) * 16384;                                      \
        _Pragma("unroll")                                                     \
        for (int j = 0; j < 4; j++) {                                         \
            size_t g_ = (size_t)frow[j] * 512 + (kc) * 32 + fc[j] * 8;        \
            cp16(s_ + foff[j],         Ag + g_);                              \
            cp16(s_ + 8192 + foff[j],  Bg + g_);                              \
        }                                                                     \
        asm volatile("cp.async.commit_group;");                               \
    } while (0)

    float acc[4][8][4];
#pragma unroll
    for (int i = 0; i < 4; i++)
#pragma unroll
        for (int j = 0; j < 8; j++)
#pragma unroll
            for (int k = 0; k < 4; k++) acc[i][j][k] = 0.f;

    const int rA_base = wm * 64 + (lane & 7) + ((lane >> 3) & 1) * 8;
    const uint32_t kbA = ((lane >> 4) & 1) * 16;
    const int rB_base = wn * 64 + (lane & 7) + ((lane >> 4) & 1) * 8;
    const uint32_t kbB = ((lane >> 3) & 1) * 16;

    FILL(0, 0);
    FILL(1, 1);
    FILL(2, 2);

    int stg = 0;
    for (int c = 0; c < 16; c++) {
        if (c <= 13)      asm volatile("cp.async.wait_group 2;");
        else if (c == 14) asm volatile("cp.async.wait_group 1;");
        else              asm volatile("cp.async.wait_group 0;");
        __syncthreads();

        const uint32_t sA = sb + stg * 16384;
        const uint32_t sB = sA + 8192;

#pragma unroll
        for (int ks = 0; ks < 2; ks++) {
            uint32_t ah[4][4], bh[4][4];
#pragma unroll
            for (int mt = 0; mt < 4; mt++) {
                int r = rA_base + mt * 16;
                uint32_t kb = kbA + ks * 32;
                ldsm4(sA + r * 64 + (kb ^ (((r >> 1) & 3) << 4)), ah[mt]);
            }
#pragma unroll
            for (int p = 0; p < 4; p++) {
                int r = rB_base + p * 16;
                uint32_t kb = kbB + ks * 32;
                ldsm4(sB + r * 64 + (kb ^ (((r >> 1) & 3) << 4)), bh[p]);
            }
#pragma unroll
            for (int mt = 0; mt < 4; mt++)
#pragma unroll
                for (int p = 0; p < 4; p++) {
                    mma_fp16(acc[mt][2 * p],     ah[mt], bh[p][0], bh[p][1]);
                    mma_fp16(acc[mt][2 * p + 1], ah[mt], bh[p][2], bh[p][3]);
                }
        }
        __syncthreads();
        if (c + 3 < 16) FILL(c + 3, stg);
        stg = (stg == 2) ? 0 : stg + 1;
    }

    // ---- epilogue: bias (+relu), fp16 stores ----
#pragma unroll
    for (int mt = 0; mt < 4; mt++) {
        int row = m0 + wm * 64 + mt * 16 + (lane >> 2);
#pragma unroll
        for (int nt = 0; nt < 8; nt++) {
            int col = n0 + wn * 64 + nt * 8 + (lane & 3) * 2;
            float2 bb = __ldg((const float2*)(biasU + col));
            float v0 = acc[mt][nt][0] + bb.x;
            float v1 = acc[mt][nt][1] + bb.y;
            float v2 = acc[mt][nt][2] + bb.x;
            float v3 = acc[mt][nt][3] + bb.y;
            if (reluU) {
                v0 = fmaxf(v0, 0.f); v1 = fmaxf(v1, 0.f);
                v2 = fmaxf(v2, 0.f); v3 = fmaxf(v3, 0.f);
            }
            *(__half2*)(CU + (size_t)row * 512 + col)       = __floats2half2_rn(v0, v1);
            *(__half2*)(CU + (size_t)(row + 8) * 512 + col) = __floats2half2_rn(v2, v3);
        }
    }
#undef FILL
}

// ---------------------------------------------------------------------------
// FP16 tensor-core causal attention per (b,n,h): T=64, D=64. 128 thr, 4 warps.
// Split-wait: Q+K group 0, V group 1 (V-wait deferred past softmax).
// Masked BEFORE scaling: masked logit = -32767/8.
// ---------------------------------------------------------------------------
__global__ __launch_bounds__(128)
void attn_fp16(const __half* __restrict__ qf, const __half* __restrict__ kf,
               const __half* __restrict__ vf, __half* __restrict__ of)
{
    __shared__ __align__(128) unsigned char sm[3 * 8192];
    const uint32_t sb = smem_u32(sm);
    const uint32_t sQ = sb, sK = sb + 8192, sV = sb + 16384;

    const int idx = blockIdx.x;
    const int h = idx & 7;
    const int n = (idx >> 3) & 255;
    const int b = idx >> 11;
    const size_t base = ((size_t)(b * T_) * N_ + n) * FEAT + h * D_;
    const int tid = threadIdx.x;
    const size_t tstride = (size_t)N_ * FEAT;

#define LOADM(ptr, moff)                                                      \
    _Pragma("unroll")                                                         \
    for (int i = 0; i < 4; i++) {                                             \
        int lin = tid + i * 128;                                              \
        int t_ = lin >> 3, q_ = lin & 7;                                      \
        cp16(sb + (moff) + t_ * 128 + ((q_ ^ (t_ & 7)) << 4),                 \
             (ptr) + base + (size_t)t_ * tstride + q_ * 8);                   \
    }
    LOADM(qf, 0);
    LOADM(kf, 8192);
    asm volatile("cp.async.commit_group;");
    LOADM(vf, 16384);
    asm volatile("cp.async.commit_group;");
#undef LOADM
    asm volatile("cp.async.wait_group 1;");
    __syncthreads();

    const int w = tid >> 5;
    const int lane = tid & 31;
    const int m0 = w * 16;
    const float NEG8 = -4095.875f;

    // ---- QK^T ----
    uint32_t aq[4][4];
    {
        int r = m0 + (lane & 7) + ((lane >> 3) & 1) * 8;
        int qc = lane >> 4;
#pragma unroll
        for (int ks = 0; ks < 4; ks++)
            ldsm4(sQ + r * 128 + (((ks * 2 + qc) ^ (r & 7)) << 4), aq[ks]);
    }

    float acc[8][4];
#pragma unroll
    for (int i = 0; i < 8; i++)
#pragma unroll
        for (int j = 0; j < 4; j++) acc[i][j] = 0.f;

    {
        int rn = (lane & 7) + ((lane >> 4) & 1) * 8;
        int kc = (lane >> 3) & 1;
#pragma unroll
        for (int ks = 0; ks < 4; ks++) {
#pragma unroll
            for (int p = 0; p < 4; p++) {
                int rt = p * 16 + rn;
                uint32_t bk[4];
                ldsm4(sK + rt * 128 + (((ks * 2 + kc) ^ (rt & 7)) << 4), bk);
                mma_fp16(acc[2 * p],     aq[ks], bk[0], bk[1]);
                mma_fp16(acc[2 * p + 1], aq[ks], bk[2], bk[3]);
            }
        }
    }

    // ---- softmax (mask before scale) ----
    const int colb = (lane & 3) * 2;
    const int r0 = m0 + (lane >> 2), r1 = r0 + 8;
    float m0v = NEG8, m1v = NEG8;
#pragma unroll
    for (int nt = 0; nt < 8; nt++) {
        int c = nt * 8 + colb;
        acc[nt][0] = (c     <= r0) ? acc[nt][0] * 0.125f : NEG8;
        acc[nt][1] = (c + 1 <= r0) ? acc[nt][1] * 0.125f : NEG8;
        acc[nt][2] = (c     <= r1) ? acc[nt][2] * 0.125f : NEG8;
        acc[nt][3] = (c + 1 <= r1) ? acc[nt][3] * 0.125f : NEG8;
        m0v = fmaxf(m0v, fmaxf(acc[nt][0], acc[nt][1]));
        m1v = fmaxf(m1v, fmaxf(acc[nt][2], acc[nt][3]));
    }
    m0v = fmaxf(m0v, __shfl_xor_sync(0xffffffffu, m0v, 1));
    m0v = fmaxf(m0v, __shfl_xor_sync(0xffffffffu, m0v, 2));
    m1v = fmaxf(m1v, __shfl_xor_sync(0xffffffffu, m1v, 1));
    m1v = fmaxf(m1v, __shfl_xor_sync(0xffffffffu, m1v, 2));

    float sum0 = 0.f, sum1 = 0.f;
#pragma unroll
    for (int nt = 0; nt < 8; nt++) {
        acc[nt][0] = __expf(acc[nt][0] - m0v);
        acc[nt][1] = __expf(acc[nt][1] - m0v);
        acc[nt][2] = __expf(acc[nt][2] - m1v);
        acc[nt][3] = __expf(acc[nt][3] - m1v);
        sum0 += acc[nt][0] + acc[nt][1];
        sum1 += acc[nt][2] + acc[nt][3];
    }
    sum0 += __shfl_xor_sync(0xffffffffu, sum0, 1);
    sum0 += __shfl_xor_sync(0xffffffffu, sum0, 2);
    sum1 += __shfl_xor_sync(0xffffffffu, sum1, 1);
    sum1 += __shfl_xor_sync(0xffffffffu, sum1, 2);
    const float inv0 = 1.f / sum0, inv1 = 1.f / sum1;

    // ---- write P (fp16) into this warp's own Q smem rows ----
#pragma unroll
    for (int nt = 0; nt < 8; nt++) {
        uint32_t o0 = r0 * 128 + ((nt ^ (r0 & 7)) << 4) + colb * 2;
        uint32_t o1 = r1 * 128 + ((nt ^ (r1 & 7)) << 4) + colb * 2;
        *(__half2*)(sm + o0) = __floats2half2_rn(acc[nt][0] * inv0, acc[nt][1] * inv0);
        *(__half2*)(sm + o1) = __floats2half2_rn(acc[nt][2] * inv1, acc[nt][3] * inv1);
    }
    asm volatile("cp.async.wait_group 0;");
    __syncwarp();

    // ---- O = P V ----
    float accO[8][4];
#pragma unroll
    for (int i = 0; i < 8; i++)
#pragma unroll
        for (int j = 0; j < 4; j++) accO[i][j] = 0.f;

    {
        int rp = m0 + (lane & 7) + ((lane >> 3) & 1) * 8;
        int pqc = lane >> 4;
        int sv = lane & 15;
        int vqc = lane >> 4;
#pragma unroll
        for (int ks = 0; ks < 4; ks++) {
            uint32_t ap[4];
            ldsm4(sQ + rp * 128 + (((ks * 2 + pqc) ^ (rp & 7)) << 4), ap);
            int rv = ks * 16 + sv;
#pragma unroll
            for (int dt = 0; dt < 4; dt++) {
                uint32_t bv[4];
                ldsm4t(sV + rv * 128 + (((dt * 2 + vqc) ^ (rv & 7)) << 4), bv);
                mma_fp16(accO[2 * dt],     ap, bv[0], bv[1]);
                mma_fp16(accO[2 * dt + 1], ap, bv[2], bv[3]);
            }
        }
    }

    // ---- store O fp16 ----
#pragma unroll
    for (int nt = 0; nt < 8; nt++) {
        int col = nt * 8 + colb;
        *(__half2*)(of + base + (size_t)r0 * tstride + col) =
            __floats2half2_rn(accO[nt][0], accO[nt][1]);
        *(__half2*)(of + base + (size_t)r1 * tstride + col) =
            __floats2half2_rn(accO[nt][2], accO[nt][3]);
    }
}

// ---------------------------------------------------------------------------
// out = LayerNorm(a + b), both inputs fp16. Optional fp32 out, optional
// fp16 out. One warp per 512-dim row.
// ---------------------------------------------------------------------------
__global__ __launch_bounds__(256)
void add_ln(const __half* __restrict__ a, const __half* __restrict__ b,
            float* __restrict__ out, __half2* __restrict__ oh)
{
    int row = blockIdx.x * 8 + (threadIdx.x >> 5);
    int l = threadIdx.x & 31;
    const uint4* pa = (const uint4*)(a + (size_t)row * 512);
    const uint4* pb = (const uint4*)(b + (size_t)row * 512);

    float x[16];
    float s = 0.f;
#pragma unroll
    for (int i = 0; i < 2; i++) {
        uint4 ua = pa[l + i * 32];
        uint4 ub = pb[l + i * 32];
        const __half2* ha = (const __half2*)&ua;
        const __half2* hb = (const __half2*)&ub;
#pragma unroll
        for (int j = 0; j < 4; j++) {
            float2 fa = __half22float2(ha[j]);
            float2 fb = __half22float2(hb[j]);
            float v0 = fa.x + fb.x, v1 = fa.y + fb.y;
            x[i * 8 + 2 * j]     = v0;
            x[i * 8 + 2 * j + 1] = v1;
            s += v0 + v1;
        }
    }
#pragma unroll
    for (int o = 16; o; o >>= 1) s += __shfl_xor_sync(0xffffffffu, s, o);
    float mean = s * (1.f / 512.f);

    float vs = 0.f;
#pragma unroll
    for (int k = 0; k < 16; k++) {
        float d = x[k] - mean;
        vs += d * d;
    }
#pragma unroll
    for (int o = 16; o; o >>= 1) vs += __shfl_xor_sync(0xffffffffu, vs, o);
    float invstd = rsqrtf(vs * (1.f / 512.f) + 1e-5f);

#pragma unroll
    for (int i = 0; i < 2; i++) {
        int c0 = (l + i * 32) * 8;
        float y[8];
#pragma unroll
        for (int j = 0; j < 8; j++) y[j] = (x[i * 8 + j] - mean) * invstd;
        if (out) {
            float* po = out + (size_t)row * 512 + c0;
            *(float4*)(po)     = make_float4(y[0], y[1], y[2], y[3]);
            *(float4*)(po + 4) = make_float4(y[4], y[5], y[6], y[7]);
        }
        if (oh) {
            __half2* ph = oh + (row * 512 + c0) / 2;
            ph[0] = __floats2half2_rn(y[0], y[1]);
            ph[1] = __floats2half2_rn(y[2], y[3]);
            ph[2] = __floats2half2_rn(y[4], y[5]);
            ph[3] = __floats2half2_rn(y[6], y[7]);
        }
    }
}

// ---------------------------------------------------------------------------
// Launch pipeline (graph-capturable: launches only)
// ---------------------------------------------------------------------------
extern "C" void kernel_launch(void* const* d_in, const int* in_sizes, int n_in,
                              void* d_out, int out_size)
{
    const float* xl = (const float*)d_in[0];
    const float* xh = (const float*)d_in[1];
    const float* te = (const float*)d_in[2];
    const float* Wq = (const float*)d_in[3];
    const float* bq = (const float*)d_in[4];
    const float* Wk = (const float*)d_in[5];
    const float* bk = (const float*)d_in[6];
    const float* Wv = (const float*)d_in[7];
    const float* bv = (const float*)d_in[8];
    const float* Wo = (const float*)d_in[9];
    const float* bo = (const float*)d_in[10];
    const float* W1 = (const float*)d_in[11];
    const float* b1 = (const float*)d_in[12];
    const float* W2 = (const float*)d_in[13];
    const float* b2 = (const float*)d_in[14];
    float* out = (float*)d_out;

    __half *hf, *wt;
    cudaGetSymbolAddress((void**)&hf, g_hf);
    cudaGetSymbolAddress((void**)&wt, g_wt);

    __half* s0f = hf + 0ull * ELEMS;
    __half* s1f = hf + 1ull * ELEMS;
    __half* qf  = hf + 2ull * ELEMS;
    __half* kf  = hf + 3ull * ELEMS;
    __half* vf  = hf + 4ull * ELEMS;
    __half* aof = hf + 5ull * ELEMS;
    __half* wof = hf + 6ull * ELEMS;
    __half* vaf = hf + 7ull * ELEMS;
    __half* f1f = hf + 8ull * ELEMS;
    __half* f2f = hf + 9ull * ELEMS;

    cudaFuncSetAttribute(gemm_fp16, cudaFuncAttributeMaxDynamicSharedMemorySize, 49152);

    const dim3 gg(4, 1024);
    const dim3 gqkv(12, 1024);
    const int nadd = ELEMS / 4 / 256;

    // 0: weight transpose (fp16 K-major)
    prep_w<<<dim3(16, 16, 6), dim3(32, 8)>>>(Wq, Wk, Wv, Wo, W1, W2, wt);
    // 1: fused residual adds -> fp16
    add_te01<<<nadd, 256>>>((const float4*)xl, (const float4*)xh, (const float4*)te,
                            (__half2*)s0f, (__half2*)s1f);
    // 2: spacer so QKV GEMM is launch index 3 (ncu capture target)
    nop_kernel<<<1, 32>>>();
    // 3: fused Q+K+V projection -> fp16  (profiled)
    gemm_fp16<<<gqkv, 128, 49152>>>(s0f, s1f,
                                    wt + 0 * WSZ, bq, qf, 0,
                                    wt + 1 * WSZ, bk, kf, 1,
                                    wt + 2 * WSZ, bv, vf, 1);
    // 4: tensor-core attention -> fp16
    attn_fp16<<<B_ * N_ * H_, 128>>>(qf, kf, vf, aof);
    // 5: Wo projection -> wof fp16
    gemm_fp16<<<gg, 128, 49152>>>(aof, 0,
                                  wt + 3 * WSZ, bo, wof, 0,
                                  0, 0, 0, 0,
                                  0, 0, 0, 0);
    // 6: val = LN(wof + s0f) -> vaf fp16
    add_ln<<<TOKENS / 8, 256>>>(wof, s0f, 0, (__half2*)vaf);
    // 7: ff1 = relu(val @ W1 + b1) -> f1f fp16
    gemm_fp16<<<gg, 128, 49152>>>(vaf, 0,
                                  wt + 4 * WSZ, b1, f1f, 1,
                                  0, 0, 0, 0,
                                  0, 0, 0, 0);
    // 8: ff2 = ff1 @ W2 + b2 -> f2f fp16
    gemm_fp16<<<gg, 128, 49152>>>(f1f, 0,
                                  wt + 5 * WSZ, b2, f2f, 0,
                                  0, 0, 0, 0,
                                  0, 0, 0, 0);
    // 9: out = LN(f2f + vaf) -> fp32
    add_ln<<<TOKENS / 8, 256>>>(f2f, vaf, out, 0);
}

// round 17
// speedup vs baseline: 1.4032x; 1.0078x over previous
#include <cuda_runtime.h>
#include <cuda_fp16.h>
#include <math.h>
#include <stdint.h>

#define B_ 8
#define T_ 64
#define N_ 256
#define H_ 8
#define D_ 64
#define FEAT 512
#define TOKENS (B_*T_*N_)          /* 131072 */
#define ELEMS  (TOKENS*FEAT)       /* 67108864 */
#define WSZ    (512*512)

// ---------------------------------------------------------------------------
// Scratch (device globals — no cudaMalloc allowed). All-fp16 intermediates.
// ---------------------------------------------------------------------------
__device__ __half g_hf[10ull * ELEMS];
__device__ __half g_wt[6 * WSZ];      // K-major fp16 weights

// ---------------------------------------------------------------------------
// Helpers
// ---------------------------------------------------------------------------
__device__ __forceinline__ uint32_t smem_u32(const void* p) {
    uint32_t a;
    asm("{ .reg .u64 t; cvta.to.shared.u64 t, %1; cvt.u32.u64 %0, t; }" : "=r"(a) : "l"(p));
    return a;
}

__device__ __forceinline__ void cp16(uint32_t dst, const void* src) {
    asm volatile("cp.async.cg.shared.global [%0], [%1], 16;"
                 :: "r"(dst), "l"(__cvta_generic_to_global(src)));
}

__device__ __forceinline__ void ldsm4(uint32_t addr, uint32_t* r) {
    asm volatile("ldmatrix.sync.aligned.m8n8.x4.shared.b16 {%0,%1,%2,%3}, [%4];"
                 : "=r"(r[0]), "=r"(r[1]), "=r"(r[2]), "=r"(r[3]) : "r"(addr));
}

__device__ __forceinline__ void ldsm4t(uint32_t addr, uint32_t* r) {
    asm volatile("ldmatrix.sync.aligned.m8n8.x4.trans.shared.b16 {%0,%1,%2,%3}, [%4];"
                 : "=r"(r[0]), "=r"(r[1]), "=r"(r[2]), "=r"(r[3]) : "r"(addr));
}

__device__ __forceinline__ void mma_fp16(float* d, const uint32_t* a,
                                         uint32_t b0, uint32_t b1) {
    asm volatile(
        "mma.sync.aligned.m16n8k16.row.col.f32.f16.f16.f32 "
        "{%0,%1,%2,%3}, {%4,%5,%6,%7}, {%8,%9}, {%0,%1,%2,%3};"
        : "+f"(d[0]), "+f"(d[1]), "+f"(d[2]), "+f"(d[3])
        : "r"(a[0]), "r"(a[1]), "r"(a[2]), "r"(a[3]), "r"(b0), "r"(b1));
}

// ---------------------------------------------------------------------------
// No-op spacer so the fused QKV GEMM lands at launch index 3 (ncu target).
// ---------------------------------------------------------------------------
__global__ void nop_kernel() {}

// ---------------------------------------------------------------------------
// Weight prep: transpose to K-major fp16. Wt[z][n][k] = fp16(W_z[k][n]).
// ---------------------------------------------------------------------------
__global__ __launch_bounds__(256)
void prep_w(const float* W0, const float* W1, const float* W2,
            const float* W3, const float* W4, const float* W5,
            __half* __restrict__ Wt)
{
    const float* Ws[6] = {W0, W1, W2, W3, W4, W5};
    const float* W = Ws[blockIdx.z];
    __shared__ float t[32][33];
    int bx = blockIdx.x * 32, by = blockIdx.y * 32;
#pragma unroll
    for (int r = 0; r < 32; r += 8)
        t[threadIdx.y + r][threadIdx.x] =
            W[(size_t)(by + threadIdx.y + r) * 512 + bx + threadIdx.x];
    __syncthreads();
    size_t base = (size_t)blockIdx.z * WSZ;
#pragma unroll
    for (int r = 0; r < 32; r += 8)
        Wt[base + (size_t)(bx + threadIdx.y + r) * 512 + by + threadIdx.x] =
            __float2half_rn(t[threadIdx.x][threadIdx.y + r]);
}

// ---------------------------------------------------------------------------
// Fused residual adds: s0 = fp16(xl+te), s1 = fp16(xh+te).
// ---------------------------------------------------------------------------
__global__ __launch_bounds__(256)
void add_te01(const float4* __restrict__ xl, const float4* __restrict__ xh,
              const float4* __restrict__ te,
              __half2* __restrict__ o0, __half2* __restrict__ o1)
{
    int i = blockIdx.x * 256 + threadIdx.x;
    float4 t = te[i];
    float4 a = xl[i];
    float4 b = xh[i];
    o0[2 * i]     = __floats2half2_rn(a.x + t.x, a.y + t.y);
    o0[2 * i + 1] = __floats2half2_rn(a.z + t.z, a.w + t.w);
    o1[2 * i]     = __floats2half2_rn(b.x + t.x, b.y + t.y);
    o1[2 * i + 1] = __floats2half2_rn(b.z + t.z, b.w + t.w);
}

// ---------------------------------------------------------------------------
// FP16 tensor-core GEMM: single pass, K-chunk 32, 4-stage cp.async pipeline
// (16KB/stage, 64KB dynamic; 2 CTAs/SM). CTA 128x128, 128 thr, 4 warps
// (64x64). Triple operand set via blockIdx.x>>2 (fused Q+K+V).
// Output fp16 (+bias, optional relu).
// ---------------------------------------------------------------------------
__global__ __launch_bounds__(128, 2)
void gemm_fp16(const __half* __restrict__ A0, const __half* __restrict__ A1,
               const __half* B0, const float* bias0, __half* C0, int relu0,
               const __half* B1, const float* bias1, __half* C1, int relu1,
               const __half* B2, const float* bias2, __half* C2, int relu2)
{
    extern __shared__ __align__(128) unsigned char smem[];
    const uint32_t sb = smem_u32(smem);

    const int tid  = threadIdx.x;
    const int lane = tid & 31;
    const int warp = tid >> 5;
    const int wm = warp >> 1, wn = warp & 1;
    const int m0 = blockIdx.y * 128;

    const int set = blockIdx.x >> 2;
    const int n0  = (blockIdx.x & 3) * 128;

    const __half* AU = (set == 0) ? A0 : A1;
    const __half* BU = (set == 0) ? B0 : ((set == 1) ? B1 : B2);
    const float* biasU = (set == 0) ? bias0 : ((set == 1) ? bias1 : bias2);
    __half* CU = (set == 0) ? C0 : ((set == 1) ? C1 : C2);
    const int reluU = (set == 0) ? relu0 : ((set == 1) ? relu1 : relu2);

    const __half* Ag = AU + (size_t)m0 * 512;
    const __half* Bg = BU + (size_t)n0 * 512;

    int frow[4], fc[4];
    uint32_t foff[4];
#pragma unroll
    for (int j = 0; j < 4; j++) {
        int lin = tid + j * 128;
        frow[j] = lin >> 2;
        fc[j]   = lin & 3;
        foff[j] = frow[j] * 64 + ((uint32_t)(fc[j] ^ ((frow[j] >> 1) & 3)) << 4);
    }

#define FILL(kc, st)                                                          \
    do {                                                                      \
        uint32_t s_ = sb + (st) * 16384;                                      \
        _Pragma("unroll")                                                     \
        for (int j = 0; j < 4; j++) {                                         \
            size_t g_ = (size_t)frow[j] * 512 + (kc) * 32 + fc[j] * 8;        \
            cp16(s_ + foff[j],         Ag + g_);                              \
            cp16(s_ + 8192 + foff[j],  Bg + g_);                              \
        }                                                                     \
        asm volatile("cp.async.commit_group;");                               \
    } while (0)

    float acc[4][8][4];
#pragma unroll
    for (int i = 0; i < 4; i++)
#pragma unroll
        for (int j = 0; j < 8; j++)
#pragma unroll
            for (int k = 0; k < 4; k++) acc[i][j][k] = 0.f;

    const int rA_base = wm * 64 + (lane & 7) + ((lane >> 3) & 1) * 8;
    const uint32_t kbA = ((lane >> 4) & 1) * 16;
    const int rB_base = wn * 64 + (lane & 7) + ((lane >> 4) & 1) * 8;
    const uint32_t kbB = ((lane >> 3) & 1) * 16;

    FILL(0, 0);
    FILL(1, 1);
    FILL(2, 2);
    FILL(3, 3);

    int stg = 0;
    for (int c = 0; c < 16; c++) {
        int rem = 15 - c;               // chunks still in flight after this one
        if (rem >= 3)      asm volatile("cp.async.wait_group 3;");
        else if (rem == 2) asm volatile("cp.async.wait_group 2;");
        else if (rem == 1) asm volatile("cp.async.wait_group 1;");
        else               asm volatile("cp.async.wait_group 0;");
        __syncthreads();

        const uint32_t sA = sb + stg * 16384;
        const uint32_t sB = sA + 8192;

#pragma unroll
        for (int ks = 0; ks < 2; ks++) {
            uint32_t ah[4][4], bh[4][4];
#pragma unroll
            for (int mt = 0; mt < 4; mt++) {
                int r = rA_base + mt * 16;
                uint32_t kb = kbA + ks * 32;
                ldsm4(sA + r * 64 + (kb ^ (((r >> 1) & 3) << 4)), ah[mt]);
            }
#pragma unroll
            for (int p = 0; p < 4; p++) {
                int r = rB_base + p * 16;
                uint32_t kb = kbB + ks * 32;
                ldsm4(sB + r * 64 + (kb ^ (((r >> 1) & 3) << 4)), bh[p]);
            }
#pragma unroll
            for (int mt = 0; mt < 4; mt++)
#pragma unroll
                for (int p = 0; p < 4; p++) {
                    mma_fp16(acc[mt][2 * p],     ah[mt], bh[p][0], bh[p][1]);
                    mma_fp16(acc[mt][2 * p + 1], ah[mt], bh[p][2], bh[p][3]);
                }
        }
        __syncthreads();
        if (c + 4 < 16) FILL(c + 4, stg);
        stg = (stg == 3) ? 0 : stg + 1;
    }

    // ---- epilogue: bias (+relu), fp16 stores ----
#pragma unroll
    for (int mt = 0; mt < 4; mt++) {
        int row = m0 + wm * 64 + mt * 16 + (lane >> 2);
#pragma unroll
        for (int nt = 0; nt < 8; nt++) {
            int col = n0 + wn * 64 + nt * 8 + (lane & 3) * 2;
            float2 bb = __ldg((const float2*)(biasU + col));
            float v0 = acc[mt][nt][0] + bb.x;
            float v1 = acc[mt][nt][1] + bb.y;
            float v2 = acc[mt][nt][2] + bb.x;
            float v3 = acc[mt][nt][3] + bb.y;
            if (reluU) {
                v0 = fmaxf(v0, 0.f); v1 = fmaxf(v1, 0.f);
                v2 = fmaxf(v2, 0.f); v3 = fmaxf(v3, 0.f);
            }
            *(__half2*)(CU + (size_t)row * 512 + col)       = __floats2half2_rn(v0, v1);
            *(__half2*)(CU + (size_t)(row + 8) * 512 + col) = __floats2half2_rn(v2, v3);
        }
    }
#undef FILL
}

// ---------------------------------------------------------------------------
// FP16 tensor-core causal attention per (b,n,h): T=64, D=64. 128 thr, 4 warps.
// Split-wait: Q+K group 0, V group 1 (V-wait deferred past softmax).
// Masked BEFORE scaling: masked logit = -32767/8.
// ---------------------------------------------------------------------------
__global__ __launch_bounds__(128)
void attn_fp16(const __half* __restrict__ qf, const __half* __restrict__ kf,
               const __half* __restrict__ vf, __half* __restrict__ of)
{
    __shared__ __align__(128) unsigned char sm[3 * 8192];
    const uint32_t sb = smem_u32(sm);
    const uint32_t sQ = sb, sK = sb + 8192, sV = sb + 16384;

    const int idx = blockIdx.x;
    const int h = idx & 7;
    const int n = (idx >> 3) & 255;
    const int b = idx >> 11;
    const size_t base = ((size_t)(b * T_) * N_ + n) * FEAT + h * D_;
    const int tid = threadIdx.x;
    const size_t tstride = (size_t)N_ * FEAT;

#define LOADM(ptr, moff)                                                      \
    _Pragma("unroll")                                                         \
    for (int i = 0; i < 4; i++) {                                             \
        int lin = tid + i * 128;                                              \
        int t_ = lin >> 3, q_ = lin & 7;                                      \
        cp16(sb + (moff) + t_ * 128 + ((q_ ^ (t_ & 7)) << 4),                 \
             (ptr) + base + (size_t)t_ * tstride + q_ * 8);                   \
    }
    LOADM(qf, 0);
    LOADM(kf, 8192);
    asm volatile("cp.async.commit_group;");
    LOADM(vf, 16384);
    asm volatile("cp.async.commit_group;");
#undef LOADM
    asm volatile("cp.async.wait_group 1;");
    __syncthreads();

    const int w = tid >> 5;
    const int lane = tid & 31;
    const int m0 = w * 16;
    const float NEG8 = -4095.875f;

    // ---- QK^T ----
    uint32_t aq[4][4];
    {
        int r = m0 + (lane & 7) + ((lane >> 3) & 1) * 8;
        int qc = lane >> 4;
#pragma unroll
        for (int ks = 0; ks < 4; ks++)
            ldsm4(sQ + r * 128 + (((ks * 2 + qc) ^ (r & 7)) << 4), aq[ks]);
    }

    float acc[8][4];
#pragma unroll
    for (int i = 0; i < 8; i++)
#pragma unroll
        for (int j = 0; j < 4; j++) acc[i][j] = 0.f;

    {
        int rn = (lane & 7) + ((lane >> 4) & 1) * 8;
        int kc = (lane >> 3) & 1;
#pragma unroll
        for (int ks = 0; ks < 4; ks++) {
#pragma unroll
            for (int p = 0; p < 4; p++) {
                int rt = p * 16 + rn;
                uint32_t bk[4];
                ldsm4(sK + rt * 128 + (((ks * 2 + kc) ^ (rt & 7)) << 4), bk);
                mma_fp16(acc[2 * p],     aq[ks], bk[0], bk[1]);
                mma_fp16(acc[2 * p + 1], aq[ks], bk[2], bk[3]);
            }
        }
    }

    // ---- softmax (mask before scale) ----
    const int colb = (lane & 3) * 2;
    const int r0 = m0 + (lane >> 2), r1 = r0 + 8;
    float m0v = NEG8, m1v = NEG8;
#pragma unroll
    for (int nt = 0; nt < 8; nt++) {
        int c = nt * 8 + colb;
        acc[nt][0] = (c     <= r0) ? acc[nt][0] * 0.125f : NEG8;
        acc[nt][1] = (c + 1 <= r0) ? acc[nt][1] * 0.125f : NEG8;
        acc[nt][2] = (c     <= r1) ? acc[nt][2] * 0.125f : NEG8;
        acc[nt][3] = (c + 1 <= r1) ? acc[nt][3] * 0.125f : NEG8;
        m0v = fmaxf(m0v, fmaxf(acc[nt][0], acc[nt][1]));
        m1v = fmaxf(m1v, fmaxf(acc[nt][2], acc[nt][3]));
    }
    m0v = fmaxf(m0v, __shfl_xor_sync(0xffffffffu, m0v, 1));
    m0v = fmaxf(m0v, __shfl_xor_sync(0xffffffffu, m0v, 2));
    m1v = fmaxf(m1v, __shfl_xor_sync(0xffffffffu, m1v, 1));
    m1v = fmaxf(m1v, __shfl_xor_sync(0xffffffffu, m1v, 2));

    float sum0 = 0.f, sum1 = 0.f;
#pragma unroll
    for (int nt = 0; nt < 8; nt++) {
        acc[nt][0] = __expf(acc[nt][0] - m0v);
        acc[nt][1] = __expf(acc[nt][1] - m0v);
        acc[nt][2] = __expf(acc[nt][2] - m1v);
        acc[nt][3] = __expf(acc[nt][3] - m1v);
        sum0 += acc[nt][0] + acc[nt][1];
        sum1 += acc[nt][2] + acc[nt][3];
    }
    sum0 += __shfl_xor_sync(0xffffffffu, sum0, 1);
    sum0 += __shfl_xor_sync(0xffffffffu, sum0, 2);
    sum1 += __shfl_xor_sync(0xffffffffu, sum1, 1);
    sum1 += __shfl_xor_sync(0xffffffffu, sum1, 2);
    const float inv0 = 1.f / sum0, inv1 = 1.f / sum1;

    // ---- write P (fp16) into this warp's own Q smem rows ----
#pragma unroll
    for (int nt = 0; nt < 8; nt++) {
        uint32_t o0 = r0 * 128 + ((nt ^ (r0 & 7)) << 4) + colb * 2;
        uint32_t o1 = r1 * 128 + ((nt ^ (r1 & 7)) << 4) + colb * 2;
        *(__half2*)(sm + o0) = __floats2half2_rn(acc[nt][0] * inv0, acc[nt][1] * inv0);
        *(__half2*)(sm + o1) = __floats2half2_rn(acc[nt][2] * inv1, acc[nt][3] * inv1);
    }
    asm volatile("cp.async.wait_group 0;");
    __syncwarp();

    // ---- O = P V ----
    float accO[8][4];
#pragma unroll
    for (int i = 0; i < 8; i++)
#pragma unroll
        for (int j = 0; j < 4; j++) accO[i][j] = 0.f;

    {
        int rp = m0 + (lane & 7) + ((lane >> 3) & 1) * 8;
        int pqc = lane >> 4;
        int sv = lane & 15;
        int vqc = lane >> 4;
#pragma unroll
        for (int ks = 0; ks < 4; ks++) {
            uint32_t ap[4];
            ldsm4(sQ + rp * 128 + (((ks * 2 + pqc) ^ (rp & 7)) << 4), ap);
            int rv = ks * 16 + sv;
#pragma unroll
            for (int dt = 0; dt < 4; dt++) {
                uint32_t bv[4];
                ldsm4t(sV + rv * 128 + (((dt * 2 + vqc) ^ (rv & 7)) << 4), bv);
                mma_fp16(accO[2 * dt],     ap, bv[0], bv[1]);
                mma_fp16(accO[2 * dt + 1], ap, bv[2], bv[3]);
            }
        }
    }

    // ---- store O fp16 ----
#pragma unroll
    for (int nt = 0; nt < 8; nt++) {
        int col = nt * 8 + colb;
        *(__half2*)(of + base + (size_t)r0 * tstride + col) =
            __floats2half2_rn(accO[nt][0], accO[nt][1]);
        *(__half2*)(of + base + (size_t)r1 * tstride + col) =
            __floats2half2_rn(accO[nt][2], accO[nt][3]);
    }
}

// ---------------------------------------------------------------------------
// out = LayerNorm(a + b), both inputs fp16. Optional fp32 out, optional
// fp16 out. One warp per 512-dim row.
// ---------------------------------------------------------------------------
__global__ __launch_bounds__(256)
void add_ln(const __half* __restrict__ a, const __half* __restrict__ b,
            float* __restrict__ out, __half2* __restrict__ oh)
{
    int row = blockIdx.x * 8 + (threadIdx.x >> 5);
    int l = threadIdx.x & 31;
    const uint4* pa = (const uint4*)(a + (size_t)row * 512);
    const uint4* pb = (const uint4*)(b + (size_t)row * 512);

    float x[16];
    float s = 0.f;
#pragma unroll
    for (int i = 0; i < 2; i++) {
        uint4 ua = pa[l + i * 32];
        uint4 ub = pb[l + i * 32];
        const __half2* ha = (const __half2*)&ua;
        const __half2* hb = (const __half2*)&ub;
#pragma unroll
        for (int j = 0; j < 4; j++) {
            float2 fa = __half22float2(ha[j]);
            float2 fb = __half22float2(hb[j]);
            float v0 = fa.x + fb.x, v1 = fa.y + fb.y;
            x[i * 8 + 2 * j]     = v0;
            x[i * 8 + 2 * j + 1] = v1;
            s += v0 + v1;
        }
    }
#pragma unroll
    for (int o = 16; o; o >>= 1) s += __shfl_xor_sync(0xffffffffu, s, o);
    float mean = s * (1.f / 512.f);

    float vs = 0.f;
#pragma unroll
    for (int k = 0; k < 16; k++) {
        float d = x[k] - mean;
        vs += d * d;
    }
#pragma unroll
    for (int o = 16; o; o >>= 1) vs += __shfl_xor_sync(0xffffffffu, vs, o);
    float invstd = rsqrtf(vs * (1.f / 512.f) + 1e-5f);

#pragma unroll
    for (int i = 0; i < 2; i++) {
        int c0 = (l + i * 32) * 8;
        float y[8];
#pragma unroll
        for (int j = 0; j < 8; j++) y[j] = (x[i * 8 + j] - mean) * invstd;
        if (out) {
            float* po = out + (size_t)row * 512 + c0;
            *(float4*)(po)     = make_float4(y[0], y[1], y[2], y[3]);
            *(float4*)(po + 4) = make_float4(y[4], y[5], y[6], y[7]);
        }
        if (oh) {
            __half2* ph = oh + (row * 512 + c0) / 2;
            ph[0] = __floats2half2_rn(y[0], y[1]);
            ph[1] = __floats2half2_rn(y[2], y[3]);
            ph[2] = __floats2half2_rn(y[4], y[5]);
            ph[3] = __floats2half2_rn(y[6], y[7]);
        }
    }
}

// ---------------------------------------------------------------------------
// Launch pipeline (graph-capturable: launches only)
// ---------------------------------------------------------------------------
extern "C" void kernel_launch(void* const* d_in, const int* in_sizes, int n_in,
                              void* d_out, int out_size)
{
    const float* xl = (const float*)d_in[0];
    const float* xh = (const float*)d_in[1];
    const float* te = (const float*)d_in[2];
    const float* Wq = (const float*)d_in[3];
    const float* bq = (const float*)d_in[4];
    const float* Wk = (const float*)d_in[5];
    const float* bk = (const float*)d_in[6];
    const float* Wv = (const float*)d_in[7];
    const float* bv = (const float*)d_in[8];
    const float* Wo = (const float*)d_in[9];
    const float* bo = (const float*)d_in[10];
    const float* W1 = (const float*)d_in[11];
    const float* b1 = (const float*)d_in[12];
    const float* W2 = (const float*)d_in[13];
    const float* b2 = (const float*)d_in[14];
    float* out = (float*)d_out;

    __half *hf, *wt;
    cudaGetSymbolAddress((void**)&hf, g_hf);
    cudaGetSymbolAddress((void**)&wt, g_wt);

    __half* s0f = hf + 0ull * ELEMS;
    __half* s1f = hf + 1ull * ELEMS;
    __half* qf  = hf + 2ull * ELEMS;
    __half* kf  = hf + 3ull * ELEMS;
    __half* vf  = hf + 4ull * ELEMS;
    __half* aof = hf + 5ull * ELEMS;
    __half* wof = hf + 6ull * ELEMS;
    __half* vaf = hf + 7ull * ELEMS;
    __half* f1f = hf + 8ull * ELEMS;
    __half* f2f = hf + 9ull * ELEMS;

    cudaFuncSetAttribute(gemm_fp16, cudaFuncAttributeMaxDynamicSharedMemorySize, 65536);

    const dim3 gg(4, 1024);
    const dim3 gqkv(12, 1024);
    const int nadd = ELEMS / 4 / 256;

    // 0: weight transpose (fp16 K-major)
    prep_w<<<dim3(16, 16, 6), dim3(32, 8)>>>(Wq, Wk, Wv, Wo, W1, W2, wt);
    // 1: fused residual adds -> fp16
    add_te01<<<nadd, 256>>>((const float4*)xl, (const float4*)xh, (const float4*)te,
                            (__half2*)s0f, (__half2*)s1f);
    // 2: spacer so QKV GEMM is launch index 3 (ncu capture target)
    nop_kernel<<<1, 32>>>();
    // 3: fused Q+K+V projection -> fp16  (profiled)
    gemm_fp16<<<gqkv, 128, 65536>>>(s0f, s1f,
                                    wt + 0 * WSZ, bq, qf, 0,
                                    wt + 1 * WSZ, bk, kf, 1,
                                    wt + 2 * WSZ, bv, vf, 1);
    // 4: tensor-core attention -> fp16
    attn_fp16<<<B_ * N_ * H_, 128>>>(qf, kf, vf, aof);
    // 5: Wo projection -> wof fp16
    gemm_fp16<<<gg, 128, 65536>>>(aof, 0,
                                  wt + 3 * WSZ, bo, wof, 0,
                                  0, 0, 0, 0,
                                  0, 0, 0, 0);
    // 6: val = LN(wof + s0f) -> vaf fp16
    add_ln<<<TOKENS / 8, 256>>>(wof, s0f, 0, (__half2*)vaf);
    // 7: ff1 = relu(val @ W1 + b1) -> f1f fp16
    gemm_fp16<<<gg, 128, 65536>>>(vaf, 0,
                                  wt + 4 * WSZ, b1, f1f, 1,
                                  0, 0, 0, 0,
                                  0, 0, 0, 0);
    // 8: ff2 = ff1 @ W2 + b2 -> f2f fp16
    gemm_fp16<<<gg, 128, 65536>>>(f1f, 0,
                                  wt + 5 * WSZ, b2, f2f, 0,
                                  0, 0, 0, 0,
                                  0, 0, 0, 0);
    // 9: out = LN(f2f + vaf) -> fp32
    add_ln<<<TOKENS / 8, 256>>>(f2f, vaf, out, 0);
}